// round 8
// baseline (speedup 1.0000x reference)
#include <cuda_runtime.h>
#include <mma.h>
#include <math.h>

using namespace nvcuda;

// ---------------- problem constants ----------------
#define BATCH   2
#define SEQ     512
#define NTOK    (BATCH*SEQ)          // 1024
#define DMODEL  1024
#define DINNER  2048
#define DSTATE  64
#define HEADDIM 64
#define NHEADS  32
#define CONVDIM (DINNER + 2*DSTATE)  // 2176
#define EPROJ   (2*DINNER + 2*DSTATE + NHEADS) // 4256
#define DCONV   4
#define VNUM    3
#define HORIZON 20
#define RMS_EPS 1e-5f
#define CHUNK   64
#define NCHUNK  (SEQ/CHUNK)          // 8

// ---------------- device scratch (no cudaMalloc allowed) ----------------
__device__ float g_zx    [NTOK * EPROJ];    // in_proj output
__device__ float g_xc    [NTOK * CONVDIM];  // conv+silu output
__device__ float g_dt    [NTOK * NHEADS];   // softplus(dt)
__device__ float g_dA    [NTOK * NHEADS];   // exp(dt*A)
__device__ float g_acum  [NTOK * NHEADS];   // within-chunk cumprod of dA
__device__ float g_state [BATCH*NHEADS*NCHUNK*HEADDIM*DSTATE]; // chunk-local end states
__device__ float g_hstart[BATCH*NHEADS*NCHUNK*HEADDIM*DSTATE]; // state at chunk start
__device__ float g_y     [NTOK * DINNER];   // scan output + D*x
__device__ float g_nrm   [NTOK * DINNER];   // gated + rmsnormed
__device__ float g_h     [NTOK * DMODEL];   // out_proj output

__device__ __forceinline__ float siluf(float x) { return x / (1.0f + expf(-x)); }
__device__ __forceinline__ float softplusf(float x) {
    return (x > 20.0f) ? x : log1pf(expf(x));
}

// ---------------- tf32 tensor-core GEMM NT: C[M,N] = A[M,K] * B[N,K]^T ----
// A row-major MxK, B row-major NxK (K contiguous). WMMA m16n16k8 tf32,
// BM=BN=64, BK=16, 128 threads = 4 warps (2x2), warp tile 32x32.
#define TBM 64
#define TBN 64
#define TBK 16
#define TLD (TBK + 8)   // padded smem row stride (24 floats, mult of 4)

__global__ void __launch_bounds__(128)
gemm_tf32(const float* __restrict__ A, const float* __restrict__ B,
          float* __restrict__ C, int M, int N, int K)
{
    __shared__ __align__(16) float As[TBM][TLD];
    __shared__ __align__(16) float Bs[TBN][TLD];

    const int tid  = threadIdx.x;
    const int warp = tid >> 5;
    const int wm   = (warp >> 1) * 32;
    const int wn   = (warp & 1) * 32;
    const int m0   = blockIdx.y * TBM;
    const int n0   = blockIdx.x * TBN;

    wmma::fragment<wmma::accumulator, 16, 16, 8, float> acc[2][2];
#pragma unroll
    for (int i = 0; i < 2; i++)
#pragma unroll
        for (int j = 0; j < 2; j++) wmma::fill_fragment(acc[i][j], 0.0f);

    // staging: 64 rows x 16 floats each; 128 threads -> each loads 8 floats/row-half
    const int lr = tid >> 1;          // 0..63
    const int lc = (tid & 1) * 8;     // 0 or 8
    const float* Ap = A + (size_t)(m0 + lr) * K + lc;
    const float* Bp = B + (size_t)(n0 + lr) * K + lc;
    const bool bok = (n0 + lr) < N;

    for (int kt = 0; kt < K; kt += TBK) {
        float4 a0 = *(const float4*)(Ap + kt);
        float4 a1 = *(const float4*)(Ap + kt + 4);
        float4 b0 = bok ? *(const float4*)(Bp + kt)     : make_float4(0.f,0.f,0.f,0.f);
        float4 b1 = bok ? *(const float4*)(Bp + kt + 4) : make_float4(0.f,0.f,0.f,0.f);
        __syncthreads();
        *(float4*)&As[lr][lc]     = a0;
        *(float4*)&As[lr][lc + 4] = a1;
        *(float4*)&Bs[lr][lc]     = b0;
        *(float4*)&Bs[lr][lc + 4] = b1;
        __syncthreads();

#pragma unroll
        for (int ks = 0; ks < 2; ks++) {
            wmma::fragment<wmma::matrix_a, 16, 16, 8, wmma::precision::tf32, wmma::row_major> af[2];
            wmma::fragment<wmma::matrix_b, 16, 16, 8, wmma::precision::tf32, wmma::col_major> bf[2];
#pragma unroll
            for (int i = 0; i < 2; i++) {
                wmma::load_matrix_sync(af[i], &As[wm + i * 16][ks * 8], TLD);
#pragma unroll
                for (int e = 0; e < af[i].num_elements; e++)
                    af[i].x[e] = wmma::__float_to_tf32(af[i].x[e]);
            }
#pragma unroll
            for (int j = 0; j < 2; j++) {
                wmma::load_matrix_sync(bf[j], &Bs[wn + j * 16][ks * 8], TLD);
#pragma unroll
                for (int e = 0; e < bf[j].num_elements; e++)
                    bf[j].x[e] = wmma::__float_to_tf32(bf[j].x[e]);
            }
#pragma unroll
            for (int i = 0; i < 2; i++)
#pragma unroll
                for (int j = 0; j < 2; j++)
                    wmma::mma_sync(acc[i][j], af[i], bf[j], acc[i][j]);
        }
    }

#pragma unroll
    for (int i = 0; i < 2; i++)
#pragma unroll
        for (int j = 0; j < 2; j++) {
            int n = n0 + wn + j * 16;
            if (n < N)   // N is always a multiple of 16 here, so tiles are all-or-nothing
                wmma::store_matrix_sync(&C[(size_t)(m0 + wm + i * 16) * N + n],
                                        acc[i][j], N, wmma::mem_row_major);
        }
}

// ---------------- conv (depthwise causal, width 4) + silu ----------------
__global__ void __launch_bounds__(256)
conv_silu_kernel(const float* __restrict__ conv_w, const float* __restrict__ conv_b)
{
    int idx = blockIdx.x * blockDim.x + threadIdx.x;
    if (idx >= NTOK * CONVDIM) return;
    int c = idx % CONVDIM;
    int t = idx / CONVDIM;
    int s = t & (SEQ - 1);
    int b = t >> 9;

    float acc = conv_b[c];
#pragma unroll
    for (int k = 0; k < DCONV; k++) {
        int ss = s + k - (DCONV - 1);
        if (ss >= 0)
            acc = fmaf(conv_w[c * DCONV + k],
                       g_zx[(size_t)(b * SEQ + ss) * EPROJ + DINNER + c], acc);
    }
    g_xc[(size_t)t * CONVDIM + c] = siluf(acc);
}

// ---------------- dt = softplus(dt_raw + bias), dA = exp(dt*A) ----------------
__global__ void __launch_bounds__(256)
dt_kernel(const float* __restrict__ dt_bias, const float* __restrict__ A_log)
{
    int idx = blockIdx.x * blockDim.x + threadIdx.x;
    if (idx >= NTOK * NHEADS) return;
    int hh = idx & (NHEADS - 1);
    int t  = idx >> 5;
    float raw = g_zx[(size_t)t * EPROJ + DINNER + CONVDIM + hh];
    float dtv = softplusf(raw + dt_bias[hh]);
    float Ah  = -expf(A_log[hh]);
    g_dt[idx] = dtv;
    g_dA[idx] = expf(dtv * Ah);
}

// ---------------- within-chunk cumulative dA products ----------------
// one thread per (b, h, chunk): 512 threads, 64 sequential multiplies each.
__global__ void __launch_bounds__(256)
acum_kernel()
{
    int idx = blockIdx.x * 256 + threadIdx.x;   // 0..511
    if (idx >= BATCH * NHEADS * NCHUNK) return;
    int chunk = idx & (NCHUNK - 1);
    int hh    = (idx >> 3) & (NHEADS - 1);
    int b     = idx >> 8;
    float a = 1.0f;
    for (int t = 0; t < CHUNK; t++) {
        int gi = (b * SEQ + chunk * CHUNK + t) * NHEADS + hh;
        a *= g_dA[gi];
        g_acum[gi] = a;
    }
}

// ---------------- pass 1: intra-chunk scan (zero initial state) ----------------
// grid (4 p-splits, NCHUNK, BATCH*NHEADS); block 128.
// thread: lp = t>>3 owns p = pb+lp; 8 n-values at n0 = (t&7)*8.
__global__ void __launch_bounds__(128)
scan_chunk_kernel(const float* __restrict__ Dp)
{
    const int bz = blockIdx.z;
    const int b  = bz >> 5;
    const int hh = bz & (NHEADS - 1);
    const int chunk = blockIdx.y;
    const int pb = blockIdx.x * 16;
    const int t  = threadIdx.x;
    const int lp = t >> 3;
    const int n0 = (t & 7) * 8;

    __shared__ __align__(16) float sB[32][64];
    __shared__ __align__(16) float sC[32][64];
    __shared__ __align__(16) float sX[32][16];
    __shared__ float sdA[32], sdt[32];

    float hst[8];
#pragma unroll
    for (int j = 0; j < 8; j++) hst[j] = 0.0f;

    const float Dh = Dp[hh];
    const size_t rowbase = (size_t)(b * SEQ) * CONVDIM;

#pragma unroll
    for (int sub = 0; sub < 2; sub++) {
        const int s0 = chunk * CHUNK + sub * 32;
        // stage B and C (32 steps x 64 states)
        for (int i = t; i < 512; i += 128) {
            int si = i >> 4, j4 = (i & 15) * 4;
            size_t r = rowbase + (size_t)(s0 + si) * CONVDIM;
            *(float4*)&sB[si][j4] = *(const float4*)&g_xc[r + DINNER + j4];
            *(float4*)&sC[si][j4] = *(const float4*)&g_xc[r + DINNER + DSTATE + j4];
        }
        // stage x (32 steps x 16 p) — exactly 128 float4s
        {
            int si = t >> 2, j4 = (t & 3) * 4;
            size_t r = rowbase + (size_t)(s0 + si) * CONVDIM;
            *(float4*)&sX[si][j4] = *(const float4*)&g_xc[r + hh * HEADDIM + pb + j4];
        }
        if (t < 32) {
            int idx = (b * SEQ + s0 + t) * NHEADS + hh;
            sdA[t] = g_dA[idx];
            sdt[t] = g_dt[idx];
        }
        __syncthreads();

        for (int si = 0; si < 32; si++) {
            float dAv = sdA[si];
            float xv  = sX[si][lp];
            float dtx = sdt[si] * xv;
            float4 b0 = *(const float4*)&sB[si][n0];
            float4 b1 = *(const float4*)&sB[si][n0 + 4];
            float4 c0 = *(const float4*)&sC[si][n0];
            float4 c1 = *(const float4*)&sC[si][n0 + 4];
            float yp;
            hst[0] = fmaf(hst[0], dAv, dtx * b0.x); yp  = hst[0] * c0.x;
            hst[1] = fmaf(hst[1], dAv, dtx * b0.y); yp += hst[1] * c0.y;
            hst[2] = fmaf(hst[2], dAv, dtx * b0.z); yp += hst[2] * c0.z;
            hst[3] = fmaf(hst[3], dAv, dtx * b0.w); yp += hst[3] * c0.w;
            hst[4] = fmaf(hst[4], dAv, dtx * b1.x); yp += hst[4] * c1.x;
            hst[5] = fmaf(hst[5], dAv, dtx * b1.y); yp += hst[5] * c1.y;
            hst[6] = fmaf(hst[6], dAv, dtx * b1.z); yp += hst[6] * c1.z;
            hst[7] = fmaf(hst[7], dAv, dtx * b1.w); yp += hst[7] * c1.w;
            yp += __shfl_xor_sync(0xffffffffu, yp, 1);
            yp += __shfl_xor_sync(0xffffffffu, yp, 2);
            yp += __shfl_xor_sync(0xffffffffu, yp, 4);
            if ((t & 7) == 0)
                g_y[(size_t)(b * SEQ + s0 + si) * DINNER + hh * HEADDIM + pb + lp] =
                    yp + Dh * xv;
        }
        __syncthreads();
    }

    // write chunk-local end state (each thread owns its 8 n's exclusively)
    size_t st = (((size_t)bz * NCHUNK + chunk) * HEADDIM + (pb + lp)) * DSTATE + n0;
    *(float4*)&g_state[st]     = make_float4(hst[0], hst[1], hst[2], hst[3]);
    *(float4*)&g_state[st + 4] = make_float4(hst[4], hst[5], hst[6], hst[7]);
}

// ---------------- pass 2: inter-chunk state scan ----------------
// one thread per (b, h, p, n): 262144 threads; 7 sequential chunk steps.
__global__ void __launch_bounds__(256)
state_scan_kernel()
{
    int idx = blockIdx.x * 256 + threadIdx.x;
    int n  = idx & 63;
    int p  = (idx >> 6) & 63;
    int bz = idx >> 12;
    int b  = bz >> 5, hh = bz & (NHEADS - 1);
    size_t base = (size_t)bz * (NCHUNK * HEADDIM * DSTATE) + (size_t)p * DSTATE + n;
    float hs = 0.0f;
#pragma unroll
    for (int c = 1; c < NCHUNK; c++) {
        float P = g_acum[((b * SEQ) + (c - 1) * CHUNK + (CHUNK - 1)) * NHEADS + hh];
        hs = fmaf(P, hs, g_state[base + (size_t)(c - 1) * (HEADDIM * DSTATE)]);
        g_hstart[base + (size_t)c * (HEADDIM * DSTATE)] = hs;
    }
}

// ---------------- pass 3: correction  y[t] += a(t) * (C[t] . h_start) ------
// grid (NCHUNK-1, BATCH*NHEADS); block 256.
__global__ void __launch_bounds__(256)
scan_correction_kernel()
{
    const int c  = blockIdx.x + 1;        // chunks 1..7
    const int bz = blockIdx.y;
    const int b  = bz >> 5, hh = bz & (NHEADS - 1);
    const int tid = threadIdx.x;

    __shared__ __align__(16) float sHt[DSTATE][HEADDIM + 4];  // [n][p] transposed
    __shared__ __align__(16) float sC [CHUNK][DSTATE];
    __shared__ float sa[CHUNK];

    // stage h_start transposed (4096 floats)
    size_t hb = (size_t)bz * (NCHUNK * HEADDIM * DSTATE) + (size_t)c * (HEADDIM * DSTATE);
#pragma unroll
    for (int k = 0; k < 4; k++) {
        int i = tid + k * 256;            // float4 index over [p][n]
        int p = i >> 4, n4 = (i & 15) * 4;
        float4 v = *(const float4*)&g_hstart[hb + (size_t)p * DSTATE + n4];
        sHt[n4 + 0][p] = v.x; sHt[n4 + 1][p] = v.y;
        sHt[n4 + 2][p] = v.z; sHt[n4 + 3][p] = v.w;
    }
    const size_t rowbase = (size_t)(b * SEQ) * CONVDIM;
#pragma unroll
    for (int k = 0; k < 4; k++) {
        int i = tid + k * 256;
        int tt = i >> 4, n4 = (i & 15) * 4;
        *(float4*)&sC[tt][n4] =
            *(const float4*)&g_xc[rowbase + (size_t)(c * CHUNK + tt) * CONVDIM
                                  + DINNER + DSTATE + n4];
    }
    if (tid < CHUNK)
        sa[tid] = g_acum[(b * SEQ + c * CHUNK + tid) * NHEADS + hh];
    __syncthreads();

#pragma unroll
    for (int it = 0; it < 4; it++) {
        int o  = tid + it * 256;          // (t, p4) work item
        int tt = o >> 4, p4 = (o & 15) * 4;
        float4 acc = make_float4(0.f, 0.f, 0.f, 0.f);
#pragma unroll 8
        for (int n = 0; n < DSTATE; n++) {
            float  cv = sC[tt][n];
            float4 hv = *(const float4*)&sHt[n][p4];
            acc.x = fmaf(cv, hv.x, acc.x);
            acc.y = fmaf(cv, hv.y, acc.y);
            acc.z = fmaf(cv, hv.z, acc.z);
            acc.w = fmaf(cv, hv.w, acc.w);
        }
        float at = sa[tt];
        size_t yi = (size_t)(b * SEQ + c * CHUNK + tt) * DINNER + hh * HEADDIM + p4;
        float4 y = *(float4*)&g_y[yi];
        y.x = fmaf(at, acc.x, y.x);
        y.y = fmaf(at, acc.y, y.y);
        y.z = fmaf(at, acc.z, y.z);
        y.w = fmaf(at, acc.w, y.w);
        *(float4*)&g_y[yi] = y;
    }
}

// ---------------- gate (silu(z)) + RMSNorm ----------------
__global__ void __launch_bounds__(256)
gate_norm_kernel(const float* __restrict__ norm_w)
{
    const int t = blockIdx.x;
    __shared__ float sg[DINNER];
    __shared__ float ssum[8];

    float local = 0.0f;
    for (int i = threadIdx.x; i < DINNER; i += 256) {
        float z = g_zx[(size_t)t * EPROJ + i];
        float g = g_y[(size_t)t * DINNER + i] * siluf(z);
        sg[i] = g;
        local = fmaf(g, g, local);
    }
#pragma unroll
    for (int off = 16; off; off >>= 1)
        local += __shfl_xor_sync(0xffffffffu, local, off);
    if ((threadIdx.x & 31) == 0) ssum[threadIdx.x >> 5] = local;
    __syncthreads();
    if (threadIdx.x < 8) {
        float v = ssum[threadIdx.x];
#pragma unroll
        for (int off = 4; off; off >>= 1)
            v += __shfl_xor_sync(0xffu, v, off);
        if (threadIdx.x == 0) ssum[0] = v;
    }
    __syncthreads();
    float scale = rsqrtf(ssum[0] / (float)DINNER + RMS_EPS);
    for (int i = threadIdx.x; i < DINNER; i += 256)
        g_nrm[(size_t)t * DINNER + i] = sg[i] * scale * norm_w[i];
}

// ---------------- decoders ----------------
__global__ void __launch_bounds__(128)
dec_cur_kernel(const float* __restrict__ w, const float* __restrict__ bias,
               float* __restrict__ out)
{
    int o = blockIdx.x * 4 + (threadIdx.x >> 5);   // 0..3071
    int lane = threadIdx.x & 31;
    int tok = o / VNUM, v = o % VNUM;
    const float* hr = &g_h[(size_t)tok * DMODEL];
    const float* wr = &w[v * DMODEL];
    float acc = 0.0f;
    for (int d = lane; d < DMODEL; d += 32) acc = fmaf(hr[d], wr[d], acc);
#pragma unroll
    for (int off = 16; off; off >>= 1)
        acc += __shfl_xor_sync(0xffffffffu, acc, off);
    if (lane == 0) out[o] = acc + bias[v];
}

__global__ void __launch_bounds__(128)
dec_fut_kernel(const float* __restrict__ w, const float* __restrict__ bias,
               float* __restrict__ out)
{
    int o = blockIdx.x * 4 + (threadIdx.x >> 5);   // 0..119
    int lane = threadIdx.x & 31;
    int b = o / (HORIZON * VNUM), j = o % (HORIZON * VNUM);
    const float* hr = &g_h[(size_t)(b * SEQ + (SEQ - 1)) * DMODEL];
    const float* wr = &w[j * DMODEL];
    float acc = 0.0f;
    for (int d = lane; d < DMODEL; d += 32) acc = fmaf(hr[d], wr[d], acc);
#pragma unroll
    for (int off = 16; off; off >>= 1)
        acc += __shfl_xor_sync(0xffffffffu, acc, off);
    if (lane == 0) out[BATCH * SEQ * VNUM + o] = acc + bias[j];
}

// ---------------- launch ----------------
extern "C" void kernel_launch(void* const* d_in, const int* in_sizes, int n_in,
                              void* d_out, int out_size)
{
    const float* embed      = (const float*)d_in[0];
    const float* in_proj_w  = (const float*)d_in[1];
    const float* conv_w     = (const float*)d_in[2];
    const float* conv_b     = (const float*)d_in[3];
    const float* dt_bias    = (const float*)d_in[4];
    const float* A_log      = (const float*)d_in[5];
    const float* Dp         = (const float*)d_in[6];
    const float* norm_w     = (const float*)d_in[7];
    const float* out_proj_w = (const float*)d_in[8];
    const float* dec_cur_w  = (const float*)d_in[9];
    const float* dec_cur_b  = (const float*)d_in[10];
    const float* dec_fut_w  = (const float*)d_in[11];
    const float* dec_fut_b  = (const float*)d_in[12];
    float* out = (float*)d_out;

    float *zx, *nrm, *h;
    cudaGetSymbolAddress((void**)&zx,  g_zx);
    cudaGetSymbolAddress((void**)&nrm, g_nrm);
    cudaGetSymbolAddress((void**)&h,   g_h);

    // 1) in_proj: [1024,1024] x [4256,1024]^T -> [1024,4256]  (tf32 TC)
    {
        dim3 grid((EPROJ + TBN - 1) / TBN, NTOK / TBM);   // 67 x 16
        gemm_tf32<<<grid, 128>>>(embed, in_proj_w, zx, NTOK, EPROJ, DMODEL);
    }
    // 2) causal conv + silu
    conv_silu_kernel<<<(NTOK * CONVDIM + 255) / 256, 256>>>(conv_w, conv_b);
    // 3) dt / dA
    dt_kernel<<<(NTOK * NHEADS + 255) / 256, 256>>>(dt_bias, A_log);
    // 3b) within-chunk cumulative dA
    acum_kernel<<<2, 256>>>();
    // 4a) intra-chunk scan
    {
        dim3 grid(4, NCHUNK, BATCH * NHEADS);
        scan_chunk_kernel<<<grid, 128>>>(Dp);
    }
    // 4b) inter-chunk state scan
    state_scan_kernel<<<(BATCH * NHEADS * HEADDIM * DSTATE) / 256, 256>>>();
    // 4c) correction
    {
        dim3 grid(NCHUNK - 1, BATCH * NHEADS);
        scan_correction_kernel<<<grid, 256>>>();
    }
    // 5) gate + rmsnorm
    gate_norm_kernel<<<NTOK, 256>>>(norm_w);
    // 6) out_proj: [1024,2048] x [1024,2048]^T -> [1024,1024]  (tf32 TC)
    {
        dim3 grid(DMODEL / TBN, NTOK / TBM);              // 16 x 16
        gemm_tf32<<<grid, 128>>>(nrm, out_proj_w, h, NTOK, DMODEL, DINNER);
    }
    // 7) decoders
    dec_cur_kernel<<<(NTOK * VNUM) / 4, 128>>>(dec_cur_w, dec_cur_b, out);
    dec_fut_kernel<<<(BATCH * HORIZON * VNUM) / 4, 128>>>(dec_fut_w, dec_fut_b, out);
}

// round 9
// speedup vs baseline: 1.3107x; 1.3107x over previous
#include <cuda_runtime.h>
#include <mma.h>
#include <math.h>

using namespace nvcuda;

// ---------------- problem constants ----------------
#define BATCH   2
#define SEQ     512
#define NTOK    (BATCH*SEQ)          // 1024
#define DMODEL  1024
#define DINNER  2048
#define DSTATE  64
#define HEADDIM 64
#define NHEADS  32
#define CONVDIM (DINNER + 2*DSTATE)  // 2176
#define EPROJ   (2*DINNER + 2*DSTATE + NHEADS) // 4256
#define DCONV   4
#define VNUM    3
#define HORIZON 20
#define RMS_EPS 1e-5f
#define CHUNK   64
#define NCHUNK  (SEQ/CHUNK)          // 8

// ---------------- device scratch (no cudaMalloc allowed) ----------------
__device__ float g_zx    [NTOK * EPROJ];    // in_proj output
__device__ float g_xc    [NTOK * CONVDIM];  // conv+silu output
__device__ float g_dt    [NTOK * NHEADS];   // softplus(dt)
__device__ float g_la    [NTOK * NHEADS];   // dt * A  (log of dA)
__device__ float g_dA    [NTOK * NHEADS];   // exp(dt*A)
__device__ float g_acum  [NTOK * NHEADS];   // within-chunk cumprod of dA
__device__ float g_state [BATCH*NHEADS*NCHUNK*HEADDIM*DSTATE]; // chunk-local end states
__device__ float g_hstart[BATCH*NHEADS*NCHUNK*HEADDIM*DSTATE]; // state at chunk start
__device__ float g_y     [NTOK * DINNER];   // scan output + D*x
__device__ float g_nrm   [NTOK * DINNER];   // gated + rmsnormed
__device__ float g_h     [NTOK * DMODEL];   // out_proj output

__device__ __forceinline__ float siluf(float x) { return x / (1.0f + expf(-x)); }
__device__ __forceinline__ float softplusf(float x) {
    return (x > 20.0f) ? x : log1pf(expf(x));
}

// ---------------- cp.async helpers ----------------
__device__ __forceinline__ void cp_async16(void* smem, const void* gmem) {
    unsigned saddr = (unsigned)__cvta_generic_to_shared(smem);
    asm volatile("cp.async.cg.shared.global [%0], [%1], 16;\n" :: "r"(saddr), "l"(gmem));
}
__device__ __forceinline__ void cp_commit() {
    asm volatile("cp.async.commit_group;\n");
}
__device__ __forceinline__ void cp_wait_all() {
    asm volatile("cp.async.wait_group 0;\n");
}

// ---------------- tf32 tensor-core GEMM NT (double-buffered cp.async) ------
// C[M,N] = A[M,K] * B[N,K]^T. A row-major MxK, B row-major NxK.
// BM=128, BN=64, BK=16; 256 threads = 8 warps (4 m x 2 n), warp tile 32x32.
#define TBM 128
#define TBN 64
#define TBK 16
#define TLD (TBK + 8)   // 24 floats = 96B row stride (16B aligned)

__global__ void __launch_bounds__(256)
gemm_tf32(const float* __restrict__ A, const float* __restrict__ B,
          float* __restrict__ C, int M, int N, int K)
{
    __shared__ __align__(16) float As[2][TBM][TLD];
    __shared__ __align__(16) float Bs[2][TBN][TLD];

    const int tid  = threadIdx.x;
    const int warp = tid >> 5;
    const int wm   = (warp & 3) * 32;    // 4 warps over M
    const int wn   = (warp >> 2) * 32;   // 2 warps over N
    const int m0   = blockIdx.y * TBM;
    const int n0   = blockIdx.x * TBN;

    wmma::fragment<wmma::accumulator, 16, 16, 8, float> acc[2][2];
#pragma unroll
    for (int i = 0; i < 2; i++)
#pragma unroll
        for (int j = 0; j < 2; j++) wmma::fill_fragment(acc[i][j], 0.0f);

    // staging decomposition: As has 512 float4 slots, Bs has 256.
    const int a_row0 = tid >> 2;             // slot tid
    const int a_row1 = (tid + 256) >> 2;     // slot tid+256
    const int a_col  = (tid & 3) * 4;
    const int b_row  = tid >> 2;             // 0..63
    const int b_col  = (tid & 3) * 4;
    const int brow_c = (n0 + b_row < N) ? (n0 + b_row) : (N - 1); // clamp (garbage cols masked at store)

    const float* Ap0 = A + (size_t)(m0 + a_row0) * K + a_col;
    const float* Ap1 = A + (size_t)(m0 + a_row1) * K + a_col;
    const float* Bp  = B + (size_t)brow_c * K + b_col;

    const int ntiles = K / TBK;

    // prologue: tile 0 -> buf 0
    cp_async16(&As[0][a_row0][a_col], Ap0);
    cp_async16(&As[0][a_row1][a_col], Ap1);
    cp_async16(&Bs[0][b_row][b_col],  Bp);
    cp_commit();

    for (int kt = 0; kt < ntiles; kt++) {
        cp_wait_all();
        __syncthreads();                 // tile kt visible; compute of kt-1 done in all warps
        if (kt + 1 < ntiles) {
            const int nb = (kt + 1) & 1;
            const size_t ko = (size_t)(kt + 1) * TBK;
            cp_async16(&As[nb][a_row0][a_col], Ap0 + ko);
            cp_async16(&As[nb][a_row1][a_col], Ap1 + ko);
            cp_async16(&Bs[nb][b_row][b_col],  Bp  + ko);
            cp_commit();
        }
        const int cb = kt & 1;
#pragma unroll
        for (int ks = 0; ks < 2; ks++) {
            wmma::fragment<wmma::matrix_a, 16, 16, 8, wmma::precision::tf32, wmma::row_major> af[2];
            wmma::fragment<wmma::matrix_b, 16, 16, 8, wmma::precision::tf32, wmma::col_major> bf[2];
#pragma unroll
            for (int i = 0; i < 2; i++) {
                wmma::load_matrix_sync(af[i], &As[cb][wm + i * 16][ks * 8], TLD);
#pragma unroll
                for (int e = 0; e < af[i].num_elements; e++)
                    af[i].x[e] = wmma::__float_to_tf32(af[i].x[e]);
            }
#pragma unroll
            for (int j = 0; j < 2; j++) {
                wmma::load_matrix_sync(bf[j], &Bs[cb][wn + j * 16][ks * 8], TLD);
#pragma unroll
                for (int e = 0; e < bf[j].num_elements; e++)
                    bf[j].x[e] = wmma::__float_to_tf32(bf[j].x[e]);
            }
#pragma unroll
            for (int i = 0; i < 2; i++)
#pragma unroll
                for (int j = 0; j < 2; j++)
                    wmma::mma_sync(acc[i][j], af[i], bf[j], acc[i][j]);
        }
    }

#pragma unroll
    for (int i = 0; i < 2; i++)
#pragma unroll
        for (int j = 0; j < 2; j++) {
            int n = n0 + wn + j * 16;
            if (n < N)   // N % 16 == 0 -> tiles are all-or-nothing
                wmma::store_matrix_sync(&C[(size_t)(m0 + wm + i * 16) * N + n],
                                        acc[i][j], N, wmma::mem_row_major);
        }
}

// ---------------- conv (depthwise causal, width 4) + silu ----------------
__global__ void __launch_bounds__(256)
conv_silu_kernel(const float* __restrict__ conv_w, const float* __restrict__ conv_b)
{
    int idx = blockIdx.x * blockDim.x + threadIdx.x;
    if (idx >= NTOK * CONVDIM) return;
    int c = idx % CONVDIM;
    int t = idx / CONVDIM;
    int s = t & (SEQ - 1);
    int b = t >> 9;

    float acc = conv_b[c];
#pragma unroll
    for (int k = 0; k < DCONV; k++) {
        int ss = s + k - (DCONV - 1);
        if (ss >= 0)
            acc = fmaf(conv_w[c * DCONV + k],
                       g_zx[(size_t)(b * SEQ + ss) * EPROJ + DINNER + c], acc);
    }
    g_xc[(size_t)t * CONVDIM + c] = siluf(acc);
}

// ---------------- dt = softplus(dt_raw + bias), la = dt*A, dA = exp(la) ----
__global__ void __launch_bounds__(256)
dt_kernel(const float* __restrict__ dt_bias, const float* __restrict__ A_log)
{
    int idx = blockIdx.x * blockDim.x + threadIdx.x;
    if (idx >= NTOK * NHEADS) return;
    int hh = idx & (NHEADS - 1);
    int t  = idx >> 5;
    float raw = g_zx[(size_t)t * EPROJ + DINNER + CONVDIM + hh];
    float dtv = softplusf(raw + dt_bias[hh]);
    float Ah  = -expf(A_log[hh]);
    float la  = dtv * Ah;
    g_dt[idx] = dtv;
    g_la[idx] = la;
    g_dA[idx] = expf(la);
}

// ---------------- within-chunk cumulative dA via warp log-scan ------------
// cumprod(exp(la)) == exp(prefix_sum(la)). One warp per (b, h, chunk).
// 512 warps total -> 64 blocks x 256 threads.
__global__ void __launch_bounds__(256)
acum_kernel()
{
    int w    = (blockIdx.x * 256 + threadIdx.x) >> 5;   // 0..511
    int lane = threadIdx.x & 31;
    if (w >= BATCH * NHEADS * NCHUNK) return;
    int chunk = w & (NCHUNK - 1);
    int hh    = (w >> 3) & (NHEADS - 1);
    int b     = w >> 8;
    int base  = (b * SEQ + chunk * CHUNK) * NHEADS + hh;

    float l0 = g_la[base + (lane * 2)     * NHEADS];
    float l1 = g_la[base + (lane * 2 + 1) * NHEADS];
    float loc = l0 + l1;
    float sc = loc;
#pragma unroll
    for (int off = 1; off < 32; off <<= 1) {
        float v = __shfl_up_sync(0xffffffffu, sc, off);
        if (lane >= off) sc += v;
    }
    float excl = sc - loc;   // exclusive prefix of pair sums
    g_acum[base + (lane * 2)     * NHEADS] = expf(excl + l0);
    g_acum[base + (lane * 2 + 1) * NHEADS] = expf(excl + loc);
}

// ---------------- pass 1: intra-chunk scan (zero initial state) ----------------
// grid (4 p-splits, NCHUNK, BATCH*NHEADS); block 128.
__global__ void __launch_bounds__(128)
scan_chunk_kernel(const float* __restrict__ Dp)
{
    const int bz = blockIdx.z;
    const int b  = bz >> 5;
    const int hh = bz & (NHEADS - 1);
    const int chunk = blockIdx.y;
    const int pb = blockIdx.x * 16;
    const int t  = threadIdx.x;
    const int lp = t >> 3;
    const int n0 = (t & 7) * 8;

    __shared__ __align__(16) float sB[32][64];
    __shared__ __align__(16) float sC[32][64];
    __shared__ __align__(16) float sX[32][16];
    __shared__ float sdA[32], sdt[32];

    float hst[8];
#pragma unroll
    for (int j = 0; j < 8; j++) hst[j] = 0.0f;

    const float Dh = Dp[hh];
    const size_t rowbase = (size_t)(b * SEQ) * CONVDIM;

#pragma unroll
    for (int sub = 0; sub < 2; sub++) {
        const int s0 = chunk * CHUNK + sub * 32;
        for (int i = t; i < 512; i += 128) {
            int si = i >> 4, j4 = (i & 15) * 4;
            size_t r = rowbase + (size_t)(s0 + si) * CONVDIM;
            *(float4*)&sB[si][j4] = *(const float4*)&g_xc[r + DINNER + j4];
            *(float4*)&sC[si][j4] = *(const float4*)&g_xc[r + DINNER + DSTATE + j4];
        }
        {
            int si = t >> 2, j4 = (t & 3) * 4;
            size_t r = rowbase + (size_t)(s0 + si) * CONVDIM;
            *(float4*)&sX[si][j4] = *(const float4*)&g_xc[r + hh * HEADDIM + pb + j4];
        }
        if (t < 32) {
            int idx = (b * SEQ + s0 + t) * NHEADS + hh;
            sdA[t] = g_dA[idx];
            sdt[t] = g_dt[idx];
        }
        __syncthreads();

        for (int si = 0; si < 32; si++) {
            float dAv = sdA[si];
            float xv  = sX[si][lp];
            float dtx = sdt[si] * xv;
            float4 b0 = *(const float4*)&sB[si][n0];
            float4 b1 = *(const float4*)&sB[si][n0 + 4];
            float4 c0 = *(const float4*)&sC[si][n0];
            float4 c1 = *(const float4*)&sC[si][n0 + 4];
            float yp;
            hst[0] = fmaf(hst[0], dAv, dtx * b0.x); yp  = hst[0] * c0.x;
            hst[1] = fmaf(hst[1], dAv, dtx * b0.y); yp += hst[1] * c0.y;
            hst[2] = fmaf(hst[2], dAv, dtx * b0.z); yp += hst[2] * c0.z;
            hst[3] = fmaf(hst[3], dAv, dtx * b0.w); yp += hst[3] * c0.w;
            hst[4] = fmaf(hst[4], dAv, dtx * b1.x); yp += hst[4] * c1.x;
            hst[5] = fmaf(hst[5], dAv, dtx * b1.y); yp += hst[5] * c1.y;
            hst[6] = fmaf(hst[6], dAv, dtx * b1.z); yp += hst[6] * c1.z;
            hst[7] = fmaf(hst[7], dAv, dtx * b1.w); yp += hst[7] * c1.w;
            yp += __shfl_xor_sync(0xffffffffu, yp, 1);
            yp += __shfl_xor_sync(0xffffffffu, yp, 2);
            yp += __shfl_xor_sync(0xffffffffu, yp, 4);
            if ((t & 7) == 0)
                g_y[(size_t)(b * SEQ + s0 + si) * DINNER + hh * HEADDIM + pb + lp] =
                    yp + Dh * xv;
        }
        __syncthreads();
    }

    size_t st = (((size_t)bz * NCHUNK + chunk) * HEADDIM + (pb + lp)) * DSTATE + n0;
    *(float4*)&g_state[st]     = make_float4(hst[0], hst[1], hst[2], hst[3]);
    *(float4*)&g_state[st + 4] = make_float4(hst[4], hst[5], hst[6], hst[7]);
}

// ---------------- pass 2: inter-chunk state scan ----------------
__global__ void __launch_bounds__(256)
state_scan_kernel()
{
    int idx = blockIdx.x * 256 + threadIdx.x;
    int n  = idx & 63;
    int p  = (idx >> 6) & 63;
    int bz = idx >> 12;
    int b  = bz >> 5, hh = bz & (NHEADS - 1);
    size_t base = (size_t)bz * (NCHUNK * HEADDIM * DSTATE) + (size_t)p * DSTATE + n;
    float hs = 0.0f;
#pragma unroll
    for (int c = 1; c < NCHUNK; c++) {
        float P = g_acum[((b * SEQ) + (c - 1) * CHUNK + (CHUNK - 1)) * NHEADS + hh];
        hs = fmaf(P, hs, g_state[base + (size_t)(c - 1) * (HEADDIM * DSTATE)]);
        g_hstart[base + (size_t)c * (HEADDIM * DSTATE)] = hs;
    }
}

// ---------------- pass 3: correction  y[t] += a(t) * (C[t] . h_start) ------
__global__ void __launch_bounds__(256)
scan_correction_kernel()
{
    const int c  = blockIdx.x + 1;        // chunks 1..7
    const int bz = blockIdx.y;
    const int b  = bz >> 5, hh = bz & (NHEADS - 1);
    const int tid = threadIdx.x;

    __shared__ __align__(16) float sHt[DSTATE][HEADDIM + 4];
    __shared__ __align__(16) float sC [CHUNK][DSTATE];
    __shared__ float sa[CHUNK];

    size_t hb = (size_t)bz * (NCHUNK * HEADDIM * DSTATE) + (size_t)c * (HEADDIM * DSTATE);
#pragma unroll
    for (int k = 0; k < 4; k++) {
        int i = tid + k * 256;
        int p = i >> 4, n4 = (i & 15) * 4;
        float4 v = *(const float4*)&g_hstart[hb + (size_t)p * DSTATE + n4];
        sHt[n4 + 0][p] = v.x; sHt[n4 + 1][p] = v.y;
        sHt[n4 + 2][p] = v.z; sHt[n4 + 3][p] = v.w;
    }
    const size_t rowbase = (size_t)(b * SEQ) * CONVDIM;
#pragma unroll
    for (int k = 0; k < 4; k++) {
        int i = tid + k * 256;
        int tt = i >> 4, n4 = (i & 15) * 4;
        *(float4*)&sC[tt][n4] =
            *(const float4*)&g_xc[rowbase + (size_t)(c * CHUNK + tt) * CONVDIM
                                  + DINNER + DSTATE + n4];
    }
    if (tid < CHUNK)
        sa[tid] = g_acum[(b * SEQ + c * CHUNK + tid) * NHEADS + hh];
    __syncthreads();

#pragma unroll
    for (int it = 0; it < 4; it++) {
        int o  = tid + it * 256;
        int tt = o >> 4, p4 = (o & 15) * 4;
        float4 acc = make_float4(0.f, 0.f, 0.f, 0.f);
#pragma unroll 8
        for (int n = 0; n < DSTATE; n++) {
            float  cv = sC[tt][n];
            float4 hv = *(const float4*)&sHt[n][p4];
            acc.x = fmaf(cv, hv.x, acc.x);
            acc.y = fmaf(cv, hv.y, acc.y);
            acc.z = fmaf(cv, hv.z, acc.z);
            acc.w = fmaf(cv, hv.w, acc.w);
        }
        float at = sa[tt];
        size_t yi = (size_t)(b * SEQ + c * CHUNK + tt) * DINNER + hh * HEADDIM + p4;
        float4 y = *(float4*)&g_y[yi];
        y.x = fmaf(at, acc.x, y.x);
        y.y = fmaf(at, acc.y, y.y);
        y.z = fmaf(at, acc.z, y.z);
        y.w = fmaf(at, acc.w, y.w);
        *(float4*)&g_y[yi] = y;
    }
}

// ---------------- gate (silu(z)) + RMSNorm ----------------
__global__ void __launch_bounds__(256)
gate_norm_kernel(const float* __restrict__ norm_w)
{
    const int t = blockIdx.x;
    __shared__ float sg[DINNER];
    __shared__ float ssum[8];

    float local = 0.0f;
    for (int i = threadIdx.x; i < DINNER; i += 256) {
        float z = g_zx[(size_t)t * EPROJ + i];
        float g = g_y[(size_t)t * DINNER + i] * siluf(z);
        sg[i] = g;
        local = fmaf(g, g, local);
    }
#pragma unroll
    for (int off = 16; off; off >>= 1)
        local += __shfl_xor_sync(0xffffffffu, local, off);
    if ((threadIdx.x & 31) == 0) ssum[threadIdx.x >> 5] = local;
    __syncthreads();
    if (threadIdx.x < 8) {
        float v = ssum[threadIdx.x];
#pragma unroll
        for (int off = 4; off; off >>= 1)
            v += __shfl_xor_sync(0xffu, v, off);
        if (threadIdx.x == 0) ssum[0] = v;
    }
    __syncthreads();
    float scale = rsqrtf(ssum[0] / (float)DINNER + RMS_EPS);
    for (int i = threadIdx.x; i < DINNER; i += 256)
        g_nrm[(size_t)t * DINNER + i] = sg[i] * scale * norm_w[i];
}

// ---------------- decoders ----------------
__global__ void __launch_bounds__(128)
dec_cur_kernel(const float* __restrict__ w, const float* __restrict__ bias,
               float* __restrict__ out)
{
    int o = blockIdx.x * 4 + (threadIdx.x >> 5);   // 0..3071
    int lane = threadIdx.x & 31;
    int tok = o / VNUM, v = o % VNUM;
    const float* hr = &g_h[(size_t)tok * DMODEL];
    const float* wr = &w[v * DMODEL];
    float acc = 0.0f;
    for (int d = lane; d < DMODEL; d += 32) acc = fmaf(hr[d], wr[d], acc);
#pragma unroll
    for (int off = 16; off; off >>= 1)
        acc += __shfl_xor_sync(0xffffffffu, acc, off);
    if (lane == 0) out[o] = acc + bias[v];
}

__global__ void __launch_bounds__(128)
dec_fut_kernel(const float* __restrict__ w, const float* __restrict__ bias,
               float* __restrict__ out)
{
    int o = blockIdx.x * 4 + (threadIdx.x >> 5);   // 0..119
    int lane = threadIdx.x & 31;
    int b = o / (HORIZON * VNUM), j = o % (HORIZON * VNUM);
    const float* hr = &g_h[(size_t)(b * SEQ + (SEQ - 1)) * DMODEL];
    const float* wr = &w[j * DMODEL];
    float acc = 0.0f;
    for (int d = lane; d < DMODEL; d += 32) acc = fmaf(hr[d], wr[d], acc);
#pragma unroll
    for (int off = 16; off; off >>= 1)
        acc += __shfl_xor_sync(0xffffffffu, acc, off);
    if (lane == 0) out[BATCH * SEQ * VNUM + o] = acc + bias[j];
}

// ---------------- launch ----------------
extern "C" void kernel_launch(void* const* d_in, const int* in_sizes, int n_in,
                              void* d_out, int out_size)
{
    const float* embed      = (const float*)d_in[0];
    const float* in_proj_w  = (const float*)d_in[1];
    const float* conv_w     = (const float*)d_in[2];
    const float* conv_b     = (const float*)d_in[3];
    const float* dt_bias    = (const float*)d_in[4];
    const float* A_log      = (const float*)d_in[5];
    const float* Dp         = (const float*)d_in[6];
    const float* norm_w     = (const float*)d_in[7];
    const float* out_proj_w = (const float*)d_in[8];
    const float* dec_cur_w  = (const float*)d_in[9];
    const float* dec_cur_b  = (const float*)d_in[10];
    const float* dec_fut_w  = (const float*)d_in[11];
    const float* dec_fut_b  = (const float*)d_in[12];
    float* out = (float*)d_out;

    float *zx, *nrm, *h;
    cudaGetSymbolAddress((void**)&zx,  g_zx);
    cudaGetSymbolAddress((void**)&nrm, g_nrm);
    cudaGetSymbolAddress((void**)&h,   g_h);

    // 1) in_proj: [1024,1024] x [4256,1024]^T -> [1024,4256]  (tf32 TC, pipelined)
    {
        dim3 grid((EPROJ + TBN - 1) / TBN, NTOK / TBM);   // 67 x 8
        gemm_tf32<<<grid, 256>>>(embed, in_proj_w, zx, NTOK, EPROJ, DMODEL);
    }
    // 2) causal conv + silu
    conv_silu_kernel<<<(NTOK * CONVDIM + 255) / 256, 256>>>(conv_w, conv_b);
    // 3) dt / la / dA
    dt_kernel<<<(NTOK * NHEADS + 255) / 256, 256>>>(dt_bias, A_log);
    // 3b) within-chunk cumulative dA (warp log-scan)
    acum_kernel<<<64, 256>>>();
    // 4a) intra-chunk scan
    {
        dim3 grid(4, NCHUNK, BATCH * NHEADS);
        scan_chunk_kernel<<<grid, 128>>>(Dp);
    }
    // 4b) inter-chunk state scan
    state_scan_kernel<<<(BATCH * NHEADS * HEADDIM * DSTATE) / 256, 256>>>();
    // 4c) correction
    {
        dim3 grid(NCHUNK - 1, BATCH * NHEADS);
        scan_correction_kernel<<<grid, 256>>>();
    }
    // 5) gate + rmsnorm
    gate_norm_kernel<<<NTOK, 256>>>(norm_w);
    // 6) out_proj: [1024,2048] x [1024,2048]^T -> [1024,1024]  (tf32 TC, pipelined)
    {
        dim3 grid(DMODEL / TBN, NTOK / TBM);              // 16 x 8
        gemm_tf32<<<grid, 256>>>(nrm, out_proj_w, h, NTOK, DMODEL, DINNER);
    }
    // 7) decoders
    dec_cur_kernel<<<(NTOK * VNUM) / 4, 128>>>(dec_cur_w, dec_cur_b, out);
    dec_fut_kernel<<<(BATCH * HORIZON * VNUM) / 4, 128>>>(dec_fut_w, dec_fut_b, out);
}